// round 8
// baseline (speedup 1.0000x reference)
#include <cuda_runtime.h>
#include <cuda_fp16.h>
#include <cstdint>
#include <math.h>

#define BATCH 256
#define SEQL  196
#define CDIM  768
#define KCODE 2048
#define MTOT  (BATCH*SEQL)   // 50176

// ---------------------------------------------------------------------------
// scratch (no cudaMalloc allowed)
// ---------------------------------------------------------------------------
__device__ float  g_codeNorm[KCODE];
__device__ int    g_idx[MTOT];
__device__ float  g_att[MTOT];
__device__ float  g_mask[MTOT];
__device__ __half g_Ahi[(size_t)MTOT * CDIM];   // 77 MB
__device__ __half g_Alo[(size_t)MTOT * CDIM];   // 77 MB
__device__ __half g_Bhi[(size_t)KCODE * CDIM];  // 3.1 MB
__device__ __half g_Blo[(size_t)KCODE * CDIM];  // 3.1 MB

// ---------------------------------------------------------------------------
// helpers
// ---------------------------------------------------------------------------
__device__ __forceinline__ uint32_t smem_u32(const void* p) {
    uint32_t a;
    asm("{ .reg .u64 t; cvta.to.shared.u64 t, %1; cvt.u32.u64 %0, t; }"
        : "=r"(a) : "l"(p));
    return a;
}

__device__ __forceinline__ void cp16(uint32_t saddr, const void* gaddr) {
    asm volatile("cp.async.ca.shared.global [%0], [%1], 16;"
                 :: "r"(saddr), "l"(gaddr));
}
#define CP_COMMIT() asm volatile("cp.async.commit_group;" ::: "memory")
#define CP_WAIT1()  asm volatile("cp.async.wait_group 1;" ::: "memory")
#define CP_WAIT0()  asm volatile("cp.async.wait_group 0;" ::: "memory")

__device__ __forceinline__ void ldsm_x4(uint32_t& r0, uint32_t& r1,
                                        uint32_t& r2, uint32_t& r3,
                                        uint32_t addr) {
    asm volatile("ldmatrix.sync.aligned.m8n8.x4.shared.b16 {%0,%1,%2,%3}, [%4];"
                 : "=r"(r0), "=r"(r1), "=r"(r2), "=r"(r3) : "r"(addr));
}

__device__ __forceinline__ void mma16816(float& c0, float& c1, float& c2, float& c3,
                                         uint32_t a0, uint32_t a1, uint32_t a2, uint32_t a3,
                                         uint32_t b0, uint32_t b1) {
    asm volatile("mma.sync.aligned.m16n8k16.row.col.f32.f16.f16.f32 "
                 "{%0,%1,%2,%3}, {%4,%5,%6,%7}, {%8,%9}, {%0,%1,%2,%3};"
                 : "+f"(c0), "+f"(c1), "+f"(c2), "+f"(c3)
                 : "r"(a0), "r"(a1), "r"(a2), "r"(a3), "r"(b0), "r"(b1));
}

// ---------------------------------------------------------------------------
// convert: float -> (fp16 hi, fp16 lo)
// ---------------------------------------------------------------------------
__global__ void convert_A_kernel(const float* __restrict__ src, int n4) {
    int i = blockIdx.x * blockDim.x + threadIdx.x;
    if (i >= n4) return;
    float4 v = reinterpret_cast<const float4*>(src)[i];
    __half h0 = __float2half_rn(v.x), h1 = __float2half_rn(v.y);
    __half h2 = __float2half_rn(v.z), h3 = __float2half_rn(v.w);
    __half l0 = __float2half_rn(v.x - __half2float(h0));
    __half l1 = __float2half_rn(v.y - __half2float(h1));
    __half l2 = __float2half_rn(v.z - __half2float(h2));
    __half l3 = __float2half_rn(v.w - __half2float(h3));
    __half2* hp = reinterpret_cast<__half2*>(g_Ahi) + 2 * (size_t)i;
    __half2* lp = reinterpret_cast<__half2*>(g_Alo) + 2 * (size_t)i;
    hp[0] = __halves2half2(h0, h1); hp[1] = __halves2half2(h2, h3);
    lp[0] = __halves2half2(l0, l1); lp[1] = __halves2half2(l2, l3);
}

__global__ void convert_B_kernel(const float* __restrict__ src, int n4) {
    int i = blockIdx.x * blockDim.x + threadIdx.x;
    if (i >= n4) return;
    float4 v = reinterpret_cast<const float4*>(src)[i];
    __half h0 = __float2half_rn(v.x), h1 = __float2half_rn(v.y);
    __half h2 = __float2half_rn(v.z), h3 = __float2half_rn(v.w);
    __half l0 = __float2half_rn(v.x - __half2float(h0));
    __half l1 = __float2half_rn(v.y - __half2float(h1));
    __half l2 = __float2half_rn(v.z - __half2float(h2));
    __half l3 = __float2half_rn(v.w - __half2float(h3));
    __half2* hp = reinterpret_cast<__half2*>(g_Bhi) + 2 * (size_t)i;
    __half2* lp = reinterpret_cast<__half2*>(g_Blo) + 2 * (size_t)i;
    hp[0] = __halves2half2(h0, h1); hp[1] = __halves2half2(h2, h3);
    lp[0] = __halves2half2(l0, l1); lp[1] = __halves2half2(l2, l3);
}

// ---------------------------------------------------------------------------
// codebook row norms ||e||^2 (fp32 exact)
// ---------------------------------------------------------------------------
__global__ void codenorm_kernel(const float* __restrict__ cb) {
    int k = blockIdx.x;
    const float* row = cb + (size_t)k * CDIM;
    float s = 0.f;
    for (int c = threadIdx.x; c < CDIM; c += blockDim.x) {
        float v = row[c];
        s += v * v;
    }
    for (int o = 16; o; o >>= 1) s += __shfl_down_sync(0xffffffffu, s, o);
    __shared__ float red[8];
    int lane = threadIdx.x & 31, wid = threadIdx.x >> 5;
    if (lane == 0) red[wid] = s;
    __syncthreads();
    if (threadIdx.x == 0) {
        float t = 0.f;
        for (int w = 0; w < (int)(blockDim.x >> 5); w++) t += red[w];
        g_codeNorm[k] = t;
    }
}

// ---------------------------------------------------------------------------
// HMMA distance GEMM + fused argmin.
// CTA tile 128(M) x 256(N), 8 warps (2M x 4N), warp tile 64x64.
// k-step 32 (two 16-k sub-steps per barrier), 3-stage cp.async pipeline,
// lookahead 1, issue-before-wait, ONE sync per 32-k step (192 barriers total).
// dot = Ahi*Bhi + Ahi*Blo + Alo*Bhi (fp32 acc), d = ||e||^2 - 2*dot.
// ---------------------------------------------------------------------------
#define LDAB   48                   // bytes per SMEM row (16 halfs + 8 pad)
#define AMAT_B (128 * LDAB)         // 6144
#define BMAT_B (256 * LDAB)         // 12288
#define OFF_AH 0
#define OFF_AL (AMAT_B)
#define OFF_BH (2 * AMAT_B)
#define OFF_BL (2 * AMAT_B + BMAT_B)
#define SUB_B  (2 * AMAT_B + 2 * BMAT_B)    // 36864 per 16-k sub-stage
#define STAGE_B (2 * SUB_B)                  // 73728 per 32-k stage
#define NSTAGE  3
#define SMEM_B  (NSTAGE * STAGE_B)           // 221184
#define K32     (CDIM / 32)                  // 24 k32-steps per n-tile
#define NTILES  (KCODE / 256)                // 8

__global__ void __launch_bounds__(256, 1) vq_hmma_kernel() {
    extern __shared__ char smem[];
    const uint32_t sb = smem_u32(smem);

    const int tid   = threadIdx.x;
    const int lane  = tid & 31;
    const int warp  = tid >> 5;
    const int warpM = warp >> 2;       // 0..1
    const int warpN = warp & 3;        // 0..3
    const int tg    = lane & 3;        // 0..3
    const int grp8  = lane >> 2;       // 0..7
    const int m0    = blockIdx.x * 128;

    // cp.async mapping: thread -> 6 x 16B chunks per 16-k sub (A row + 2 B rows)
    const int ldRow  = tid >> 1;       // 0..127
    const int ldHalf = tid & 1;        // 0..1
    const uint32_t aOff  = (uint32_t)(ldRow * LDAB + ldHalf * 16);
    const uint32_t bOff0 = aOff;
    const uint32_t bOff1 = (uint32_t)((ldRow + 128) * LDAB + ldHalf * 16);
    const __half* AhiBase = g_Ahi + (size_t)(m0 + ldRow) * CDIM + ldHalf * 8;
    const __half* AloBase = g_Alo + (size_t)(m0 + ldRow) * CDIM + ldHalf * 8;
    const size_t  bG0 = (size_t)ldRow * CDIM + ldHalf * 8;
    const size_t  bG1 = (size_t)(ldRow + 128) * CDIM + ldHalf * 8;

    // ldmatrix addresses (within a sub-stage, relative)
    const uint32_t aRowOff =
        (uint32_t)((warpM * 64 + (lane & 15)) * LDAB + (lane >> 4) * 16);
    const uint32_t bRowOff =
        (uint32_t)((warpN * 64 + ((lane >> 4) << 3) + (lane & 7)) * LDAB +
                   ((lane >> 3) & 1) * 16);

    // per-thread argmin: 8 owned row-slots (4 mf x 2 halves)
    float best[8];
    int   bidx[8];
#pragma unroll
    for (int i = 0; i < 8; i++) { best[i] = 3.4e38f; bidx[i] = 0; }

    // issue cursor over 32-k steps
    int in = 0, ik = 0;

    // prologue: issue data step 0 (both 16-k subs) into stage 0
    {
        uint32_t st = sb;
        const __half* bh0 = g_Bhi;
        const __half* bl0 = g_Blo;
#pragma unroll
        for (int s = 0; s < 2; s++) {
            int gk = s * 16;   // ik = 0
            uint32_t ss = st + (uint32_t)s * SUB_B;
            cp16(ss + OFF_AH + aOff, AhiBase + gk);
            cp16(ss + OFF_AL + aOff, AloBase + gk);
            cp16(ss + OFF_BH + bOff0, bh0 + bG0 + gk);
            cp16(ss + OFF_BH + bOff1, bh0 + bG1 + gk);
            cp16(ss + OFF_BL + bOff0, bl0 + bG0 + gk);
            cp16(ss + OFF_BL + bOff1, bl0 + bG1 + gk);
        }
        CP_COMMIT();
        if (++ik == K32) { ik = 0; in++; }
    }

    for (int nt = 0; nt < NTILES; nt++) {
        const int n0 = nt * 256;

        float acc[4][8][4];
#pragma unroll
        for (int mf = 0; mf < 4; mf++)
#pragma unroll
            for (int nf = 0; nf < 8; nf++)
#pragma unroll
                for (int c = 0; c < 4; c++) acc[mf][nf][c] = 0.f;

        for (int ks = 0; ks < K32; ks++) {
            const int g = nt * K32 + ks;

            // issue data g+1 into stage (g+1)%3 BEFORE the wait.
            // stage (g+1)%3 was consumed at step g-2; all warps passed
            // barrier g-1 -> safe to refill pre-barrier.
            if (in < NTILES) {
                uint32_t st = sb + (uint32_t)((g + 1) % NSTAGE) * STAGE_B;
                const __half* bh0 = g_Bhi + (size_t)in * 256 * CDIM;
                const __half* bl0 = g_Blo + (size_t)in * 256 * CDIM;
#pragma unroll
                for (int s = 0; s < 2; s++) {
                    int gk = ik * 32 + s * 16;
                    uint32_t ss = st + (uint32_t)s * SUB_B;
                    cp16(ss + OFF_AH + aOff, AhiBase + gk);
                    cp16(ss + OFF_AL + aOff, AloBase + gk);
                    cp16(ss + OFF_BH + bOff0, bh0 + bG0 + gk);
                    cp16(ss + OFF_BH + bOff1, bh0 + bG1 + gk);
                    cp16(ss + OFF_BL + bOff0, bl0 + bG0 + gk);
                    cp16(ss + OFF_BL + bOff1, bl0 + bG1 + gk);
                }
                if (++ik == K32) { ik = 0; in++; }
            }
            CP_COMMIT();   // unconditional: keeps group counting exact at tail

            CP_WAIT1();    // newest outstanding = g+1 -> data g ready
            __syncthreads();

            const uint32_t stg = sb + (uint32_t)(g % NSTAGE) * STAGE_B;

            // two 16-k sub-steps, no barrier between
#pragma unroll
            for (int s = 0; s < 2; s++) {
                const uint32_t stage = stg + (uint32_t)s * SUB_B;

                uint32_t ah[4][4], al[4][4];
#pragma unroll
                for (int mf = 0; mf < 4; mf++) {
                    uint32_t a = stage + aRowOff + (uint32_t)(mf * 16 * LDAB);
                    ldsm_x4(ah[mf][0], ah[mf][1], ah[mf][2], ah[mf][3], a + OFF_AH);
                    ldsm_x4(al[mf][0], al[mf][1], al[mf][2], al[mf][3], a + OFF_AL);
                }

                // process B in two 32-column halves to cap register liveness
#pragma unroll
                for (int h = 0; h < 2; h++) {
                    uint32_t bh[4][2], bl[4][2];
#pragma unroll
                    for (int p = 0; p < 2; p++) {
                        uint32_t b = stage + bRowOff +
                                     (uint32_t)((h * 32 + p * 16) * LDAB);
                        uint32_t r0, r1, r2, r3;
                        ldsm_x4(r0, r1, r2, r3, b + OFF_BH);
                        bh[p * 2][0] = r0; bh[p * 2][1] = r1;
                        bh[p * 2 + 1][0] = r2; bh[p * 2 + 1][1] = r3;
                        ldsm_x4(r0, r1, r2, r3, b + OFF_BL);
                        bl[p * 2][0] = r0; bl[p * 2][1] = r1;
                        bl[p * 2 + 1][0] = r2; bl[p * 2 + 1][1] = r3;
                    }
#pragma unroll
                    for (int mf = 0; mf < 4; mf++) {
#pragma unroll
                        for (int nf = 0; nf < 4; nf++) {
                            float* c = acc[mf][h * 4 + nf];
                            mma16816(c[0], c[1], c[2], c[3],
                                     ah[mf][0], ah[mf][1], ah[mf][2], ah[mf][3],
                                     bh[nf][0], bh[nf][1]);
                            mma16816(c[0], c[1], c[2], c[3],
                                     ah[mf][0], ah[mf][1], ah[mf][2], ah[mf][3],
                                     bl[nf][0], bl[nf][1]);
                            mma16816(c[0], c[1], c[2], c[3],
                                     al[mf][0], al[mf][1], al[mf][2], al[mf][3],
                                     bh[nf][0], bh[nf][1]);
                        }
                    }
                }
            }
        }

        // fold this n-tile into running argmin (registers only)
#pragma unroll
        for (int nf = 0; nf < 8; nf++) {
            int n = n0 + warpN * 64 + nf * 8 + tg * 2;
            float cn0 = __ldg(&g_codeNorm[n]);
            float cn1 = __ldg(&g_codeNorm[n + 1]);
#pragma unroll
            for (int mf = 0; mf < 4; mf++) {
                float d0 = cn0 - 2.f * acc[mf][nf][0];
                float d1 = cn1 - 2.f * acc[mf][nf][1];
                float d2 = cn0 - 2.f * acc[mf][nf][2];
                float d3 = cn1 - 2.f * acc[mf][nf][3];
                if (d0 < best[2 * mf]) { best[2 * mf] = d0; bidx[2 * mf] = n; }
                if (d1 < best[2 * mf]) { best[2 * mf] = d1; bidx[2 * mf] = n + 1; }
                if (d2 < best[2 * mf + 1]) { best[2 * mf + 1] = d2; bidx[2 * mf + 1] = n; }
                if (d3 < best[2 * mf + 1]) { best[2 * mf + 1] = d3; bidx[2 * mf + 1] = n + 1; }
            }
        }
    }

    // drain remaining (empty) groups before reusing smem
    CP_WAIT0();
    __syncthreads();

    // cross-thread reduce: row r owned by 16 threads (4 N-warps x 4 tg)
    float* sV = reinterpret_cast<float*>(smem);            // [128][16]
    int*   sI = reinterpret_cast<int*>(smem + 128 * 16 * 4);
    const int slot = warpN * 4 + tg;
#pragma unroll
    for (int mf = 0; mf < 4; mf++) {
        int r0 = warpM * 64 + mf * 16 + grp8;
        sV[r0 * 16 + slot] = best[2 * mf];
        sI[r0 * 16 + slot] = bidx[2 * mf];
        sV[(r0 + 8) * 16 + slot] = best[2 * mf + 1];
        sI[(r0 + 8) * 16 + slot] = bidx[2 * mf + 1];
    }
    __syncthreads();
    if (tid < 128) {
        float bv = sV[tid * 16];
        int   bi = sI[tid * 16];
#pragma unroll
        for (int t = 1; t < 16; t++) {
            float v = sV[tid * 16 + t];
            int   ii = sI[tid * 16 + t];
            if (v < bv || (v == bv && ii < bi)) { bv = v; bi = ii; }
        }
        g_idx[m0 + tid] = bi;
    }
}

// ---------------------------------------------------------------------------
// att[t] = relu(dot(codebook[idx[t]], att_w[:,1])), + idx written as float
// ---------------------------------------------------------------------------
__global__ void att_kernel(const float* __restrict__ cb,
                           const float* __restrict__ att_w,
                           float* __restrict__ out_idx_f, int write_idx) {
    int gw   = (blockIdx.x * blockDim.x + threadIdx.x) >> 5;
    int lane = threadIdx.x & 31;
    if (gw >= MTOT) return;
    int idx = g_idx[gw];
    const float* row = cb + (size_t)idx * CDIM;
    float s = 0.f;
    for (int c = lane; c < CDIM; c += 32)
        s = fmaf(row[c], att_w[c * 3 + 1], s);
    for (int o = 16; o; o >>= 1) s += __shfl_down_sync(0xffffffffu, s, o);
    if (lane == 0) {
        g_att[gw] = fmaxf(s, 0.f);
        if (write_idx) out_idx_f[gw] = (float)idx;
    }
}

// ---------------------------------------------------------------------------
// softmax over L per batch -> g_mask
// ---------------------------------------------------------------------------
__global__ void softmax_kernel() {
    int b = blockIdx.x;
    int t = threadIdx.x;
    __shared__ float red[8];
    float v = (t < SEQL) ? g_att[b * SEQL + t] : -3.4e38f;

    float m = v;
    for (int o = 16; o; o >>= 1) m = fmaxf(m, __shfl_xor_sync(0xffffffffu, m, o));
    int lane = t & 31, wid = t >> 5;
    if (lane == 0) red[wid] = m;
    __syncthreads();
    if (wid == 0) {
        float x = (lane < 8) ? red[lane] : -3.4e38f;
        for (int o = 4; o; o >>= 1) x = fmaxf(x, __shfl_xor_sync(0xffffffffu, x, o));
        if (lane == 0) red[0] = x;
    }
    __syncthreads();
    float bmax = red[0];
    __syncthreads();

    float e = (t < SEQL) ? __expf(v - bmax) : 0.f;
    float s = e;
    for (int o = 16; o; o >>= 1) s += __shfl_xor_sync(0xffffffffu, s, o);
    if (lane == 0) red[wid] = s;
    __syncthreads();
    if (wid == 0) {
        float x = (lane < 8) ? red[lane] : 0.f;
        for (int o = 4; o; o >>= 1) x += __shfl_xor_sync(0xffffffffu, x, o);
        if (lane == 0) red[0] = x;
    }
    __syncthreads();
    float bsum = red[0];
    if (t < SEQL) g_mask[b * SEQL + t] = e / bsum;
}

// ---------------------------------------------------------------------------
// out[t,c] = codebook[idx[t]][c] + in[t,c] * mask[t]
// ---------------------------------------------------------------------------
__global__ void out_kernel(const float* __restrict__ in,
                           const float* __restrict__ cb,
                           float* __restrict__ out) {
    int t  = blockIdx.x;
    int c4 = threadIdx.x;          // 0..191
    float m = g_mask[t];
    int idx = g_idx[t];
    const float4* q4 = reinterpret_cast<const float4*>(cb + (size_t)idx * CDIM);
    const float4* x4 = reinterpret_cast<const float4*>(in + (size_t)t * CDIM);
    float4* o4 = reinterpret_cast<float4*>(out + (size_t)t * CDIM);
    float4 q = q4[c4];
    float4 x = x4[c4];
    o4[c4] = make_float4(fmaf(x.x, m, q.x), fmaf(x.y, m, q.y),
                         fmaf(x.z, m, q.z), fmaf(x.w, m, q.w));
}

// ---------------------------------------------------------------------------
extern "C" void kernel_launch(void* const* d_in, const int* in_sizes, int n_in,
                              void* d_out, int out_size) {
    const float* in_feas  = (const float*)d_in[0];   // [B, L, C]
    const float* codebook = (const float*)d_in[1];   // [K, C]
    const float* att_w    = (const float*)d_in[2];   // [1, C, 3]
    float* out = (float*)d_out;
    (void)in_sizes; (void)n_in;

    int write_idx = (out_size >= MTOT * CDIM + MTOT) ? 1 : 0;
    float* out_idx_f = out + (size_t)MTOT * CDIM;

    cudaFuncSetAttribute(vq_hmma_kernel,
                         cudaFuncAttributeMaxDynamicSharedMemorySize, SMEM_B);

    {
        int n4 = MTOT * CDIM / 4;   // 9,633,792
        convert_A_kernel<<<(n4 + 255) / 256, 256>>>(in_feas, n4);
    }
    {
        int n4 = KCODE * CDIM / 4;  // 393,216
        convert_B_kernel<<<(n4 + 255) / 256, 256>>>(codebook, n4);
    }
    codenorm_kernel<<<KCODE, 256>>>(codebook);

    vq_hmma_kernel<<<MTOT / 128, 256, SMEM_B>>>();

    att_kernel<<<(MTOT * 32 + 255) / 256, 256>>>(codebook, att_w, out_idx_f, write_idx);
    softmax_kernel<<<BATCH, 256>>>();
    out_kernel<<<MTOT, CDIM / 4>>>(in_feas, codebook, out);
}

// round 9
// speedup vs baseline: 1.0245x; 1.0245x over previous
#include <cuda_runtime.h>
#include <cuda_fp16.h>
#include <cstdint>
#include <math.h>

#define BATCH 256
#define SEQL  196
#define CDIM  768
#define KCODE 2048
#define MTOT  (BATCH*SEQL)   // 50176

// ---------------------------------------------------------------------------
// scratch (no cudaMalloc allowed)
// ---------------------------------------------------------------------------
__device__ float  g_codeNorm[KCODE];
__device__ int    g_idx[MTOT];
__device__ float  g_att[MTOT];
__device__ float  g_mask[MTOT];
__device__ __half g_Ahi[(size_t)MTOT * CDIM];   // 77 MB
__device__ __half g_Alo[(size_t)MTOT * CDIM];   // 77 MB
__device__ __half g_Bhi[(size_t)KCODE * CDIM];  // 3.1 MB
__device__ __half g_Blo[(size_t)KCODE * CDIM];  // 3.1 MB

// ---------------------------------------------------------------------------
// helpers
// ---------------------------------------------------------------------------
__device__ __forceinline__ uint32_t smem_u32(const void* p) {
    uint32_t a;
    asm("{ .reg .u64 t; cvta.to.shared.u64 t, %1; cvt.u32.u64 %0, t; }"
        : "=r"(a) : "l"(p));
    return a;
}

__device__ __forceinline__ void cp16(uint32_t saddr, const void* gaddr) {
    asm volatile("cp.async.ca.shared.global [%0], [%1], 16;"
                 :: "r"(saddr), "l"(gaddr));
}
#define CP_COMMIT() asm volatile("cp.async.commit_group;" ::: "memory")
#define CP_WAIT2()  asm volatile("cp.async.wait_group 2;" ::: "memory")
#define CP_WAIT0()  asm volatile("cp.async.wait_group 0;" ::: "memory")

#define GROUP_BAR(id) \
    asm volatile("bar.sync %0, 128;" :: "r"(id) : "memory")

__device__ __forceinline__ void ldsm_x4(uint32_t& r0, uint32_t& r1,
                                        uint32_t& r2, uint32_t& r3,
                                        uint32_t addr) {
    asm volatile("ldmatrix.sync.aligned.m8n8.x4.shared.b16 {%0,%1,%2,%3}, [%4];"
                 : "=r"(r0), "=r"(r1), "=r"(r2), "=r"(r3) : "r"(addr));
}

__device__ __forceinline__ void mma16816(float& c0, float& c1, float& c2, float& c3,
                                         uint32_t a0, uint32_t a1, uint32_t a2, uint32_t a3,
                                         uint32_t b0, uint32_t b1) {
    asm volatile("mma.sync.aligned.m16n8k16.row.col.f32.f16.f16.f32 "
                 "{%0,%1,%2,%3}, {%4,%5,%6,%7}, {%8,%9}, {%0,%1,%2,%3};"
                 : "+f"(c0), "+f"(c1), "+f"(c2), "+f"(c3)
                 : "r"(a0), "r"(a1), "r"(a2), "r"(a3), "r"(b0), "r"(b1));
}

// ---------------------------------------------------------------------------
// convert: float -> (fp16 hi, fp16 lo)
// ---------------------------------------------------------------------------
__global__ void convert_A_kernel(const float* __restrict__ src, int n4) {
    int i = blockIdx.x * blockDim.x + threadIdx.x;
    if (i >= n4) return;
    float4 v = reinterpret_cast<const float4*>(src)[i];
    __half h0 = __float2half_rn(v.x), h1 = __float2half_rn(v.y);
    __half h2 = __float2half_rn(v.z), h3 = __float2half_rn(v.w);
    __half l0 = __float2half_rn(v.x - __half2float(h0));
    __half l1 = __float2half_rn(v.y - __half2float(h1));
    __half l2 = __float2half_rn(v.z - __half2float(h2));
    __half l3 = __float2half_rn(v.w - __half2float(h3));
    __half2* hp = reinterpret_cast<__half2*>(g_Ahi) + 2 * (size_t)i;
    __half2* lp = reinterpret_cast<__half2*>(g_Alo) + 2 * (size_t)i;
    hp[0] = __halves2half2(h0, h1); hp[1] = __halves2half2(h2, h3);
    lp[0] = __halves2half2(l0, l1); lp[1] = __halves2half2(l2, l3);
}

__global__ void convert_B_kernel(const float* __restrict__ src, int n4) {
    int i = blockIdx.x * blockDim.x + threadIdx.x;
    if (i >= n4) return;
    float4 v = reinterpret_cast<const float4*>(src)[i];
    __half h0 = __float2half_rn(v.x), h1 = __float2half_rn(v.y);
    __half h2 = __float2half_rn(v.z), h3 = __float2half_rn(v.w);
    __half l0 = __float2half_rn(v.x - __half2float(h0));
    __half l1 = __float2half_rn(v.y - __half2float(h1));
    __half l2 = __float2half_rn(v.z - __half2float(h2));
    __half l3 = __float2half_rn(v.w - __half2float(h3));
    __half2* hp = reinterpret_cast<__half2*>(g_Bhi) + 2 * (size_t)i;
    __half2* lp = reinterpret_cast<__half2*>(g_Blo) + 2 * (size_t)i;
    hp[0] = __halves2half2(h0, h1); hp[1] = __halves2half2(h2, h3);
    lp[0] = __halves2half2(l0, l1); lp[1] = __halves2half2(l2, l3);
}

// ---------------------------------------------------------------------------
// codebook row norms ||e||^2 (fp32 exact)
// ---------------------------------------------------------------------------
__global__ void codenorm_kernel(const float* __restrict__ cb) {
    int k = blockIdx.x;
    const float* row = cb + (size_t)k * CDIM;
    float s = 0.f;
    for (int c = threadIdx.x; c < CDIM; c += blockDim.x) {
        float v = row[c];
        s += v * v;
    }
    for (int o = 16; o; o >>= 1) s += __shfl_down_sync(0xffffffffu, s, o);
    __shared__ float red[8];
    int lane = threadIdx.x & 31, wid = threadIdx.x >> 5;
    if (lane == 0) red[wid] = s;
    __syncthreads();
    if (threadIdx.x == 0) {
        float t = 0.f;
        for (int w = 0; w < (int)(blockDim.x >> 5); w++) t += red[w];
        g_codeNorm[k] = t;
    }
}

// ---------------------------------------------------------------------------
// HMMA distance GEMM + fused argmin, DUAL-GROUP version.
// 256 threads = 2 groups x 4 warps. Each group: independent 4-stage cp.async
// pipeline (own 98KB smem region, own named barrier), CTA tile 128(M)x128(N),
// warp tile 64x64 (2M x 2N warps). Group g covers codebook rows
// [g*1024, g*1024+1024) in 8 n-tiles of 128. Same math as before:
// dot = Ahi*Bhi + Ahi*Blo + Alo*Bhi (fp32 acc), d = ||e||^2 - 2*dot.
// The two groups' barrier phases decouple -> tensor-pipe bubbles overlap.
// ---------------------------------------------------------------------------
#define LDAB   48                   // bytes per SMEM row (16 halfs + 8 pad)
#define MAT_B  (128 * LDAB)         // 6144
#define OFF_AH 0
#define OFF_AL (1 * MAT_B)
#define OFF_BH (2 * MAT_B)
#define OFF_BL (3 * MAT_B)
#define STAGE_B (4 * MAT_B)         // 24576
#define NSTAGE  4
#define GROUP_B (NSTAGE * STAGE_B)  // 98304
#define SMEM_B  (2 * GROUP_B)       // 196608
#define KSTEPS  (CDIM / 16)         // 48
#define NT_G    8                   // n-tiles (of 128) per group
#define LOOKAHEAD 2

__global__ void __launch_bounds__(256, 1) vq_hmma_kernel() {
    extern __shared__ char smem[];
    const uint32_t sb = smem_u32(smem);

    const int tid   = threadIdx.x;
    const int lane  = tid & 31;
    const int warp  = tid >> 5;        // 0..7
    const int group = warp >> 2;       // 0..1
    const int wg    = warp & 3;        // warp within group
    const int warpM = wg >> 1;         // 0..1
    const int warpN = wg & 1;          // 0..1
    const int tg    = lane & 3;        // 0..3
    const int grp8  = lane >> 2;       // 0..7
    const int m0    = blockIdx.x * 128;
    const int barid = group + 1;

    const uint32_t gb = sb + (uint32_t)group * GROUP_B;

    // cp.async mapping: each of the group's 128 threads owns one row (32B =
    // 2x16B chunks) of each of the 4 matrices -> 8 cp16 per stage.
    const int ldRow = tid & 127;       // row within group's tile
    const uint32_t rowOff = (uint32_t)(ldRow * LDAB);
    const __half* AhiBase = g_Ahi + (size_t)(m0 + ldRow) * CDIM;
    const __half* AloBase = g_Alo + (size_t)(m0 + ldRow) * CDIM;
    const size_t  bRowG   = ((size_t)group * NT_G * 128 + ldRow) * CDIM;

    // ldmatrix addresses (within a stage, relative)
    const uint32_t aRowOff =
        (uint32_t)((warpM * 64 + (lane & 15)) * LDAB + (lane >> 4) * 16);
    const uint32_t bRowOff =
        (uint32_t)((warpN * 64 + ((lane >> 4) << 3) + (lane & 7)) * LDAB +
                   ((lane >> 3) & 1) * 16);

    // per-thread argmin: 8 owned row-slots (4 mf x 2 halves)
    float best[8];
    int   bidx[8];
#pragma unroll
    for (int i = 0; i < 8; i++) { best[i] = 3.4e38f; bidx[i] = 0; }

    // issue cursor (per group)
    int in = 0, ik = 0;

    // prologue: issue data steps 0..LOOKAHEAD-1
#pragma unroll
    for (int p = 0; p < LOOKAHEAD; p++) {
        uint32_t st = gb + (uint32_t)p * STAGE_B + rowOff;
        int gk = ik * 16;
        const __half* bh = g_Bhi + bRowG + (size_t)in * 128 * CDIM + gk;
        const __half* bl = g_Blo + bRowG + (size_t)in * 128 * CDIM + gk;
        cp16(st + OFF_AH,      AhiBase + gk);
        cp16(st + OFF_AH + 16, AhiBase + gk + 8);
        cp16(st + OFF_AL,      AloBase + gk);
        cp16(st + OFF_AL + 16, AloBase + gk + 8);
        cp16(st + OFF_BH,      bh);
        cp16(st + OFF_BH + 16, bh + 8);
        cp16(st + OFF_BL,      bl);
        cp16(st + OFF_BL + 16, bl + 8);
        CP_COMMIT();
        if (++ik == KSTEPS) { ik = 0; in++; }
    }

    for (int nt = 0; nt < NT_G; nt++) {
        const int n0 = group * (NT_G * 128) + nt * 128;

        float acc[4][8][4];
#pragma unroll
        for (int mf = 0; mf < 4; mf++)
#pragma unroll
            for (int nf = 0; nf < 8; nf++)
#pragma unroll
                for (int c = 0; c < 4; c++) acc[mf][nf][c] = 0.f;

        for (int ks = 0; ks < KSTEPS; ks++) {
            const int g = nt * KSTEPS + ks;

            // issue data g+2 BEFORE wait (overlaps L2); stage (g+2)%4 was
            // consumed at step g-2, all group warps passed barrier g-1.
            if (in < NT_G) {
                uint32_t st = gb +
                    (uint32_t)((g + LOOKAHEAD) & (NSTAGE - 1)) * STAGE_B + rowOff;
                int gk = ik * 16;
                const __half* bh = g_Bhi + bRowG + (size_t)in * 128 * CDIM + gk;
                const __half* bl = g_Blo + bRowG + (size_t)in * 128 * CDIM + gk;
                cp16(st + OFF_AH,      AhiBase + gk);
                cp16(st + OFF_AH + 16, AhiBase + gk + 8);
                cp16(st + OFF_AL,      AloBase + gk);
                cp16(st + OFF_AL + 16, AloBase + gk + 8);
                cp16(st + OFF_BH,      bh);
                cp16(st + OFF_BH + 16, bh + 8);
                cp16(st + OFF_BL,      bl);
                cp16(st + OFF_BL + 16, bl + 8);
                if (++ik == KSTEPS) { ik = 0; in++; }
            }
            CP_COMMIT();   // unconditional: group counting exact at tail

            CP_WAIT2();
            GROUP_BAR(barid);

            const uint32_t stage = gb + (uint32_t)(g & (NSTAGE - 1)) * STAGE_B;

            uint32_t ah[4][4], al[4][4];
#pragma unroll
            for (int mf = 0; mf < 4; mf++) {
                uint32_t a = stage + aRowOff + (uint32_t)(mf * 16 * LDAB);
                ldsm_x4(ah[mf][0], ah[mf][1], ah[mf][2], ah[mf][3], a + OFF_AH);
                ldsm_x4(al[mf][0], al[mf][1], al[mf][2], al[mf][3], a + OFF_AL);
            }

            // B in two 32-column halves to cap register liveness
#pragma unroll
            for (int h = 0; h < 2; h++) {
                uint32_t bh[4][2], bl[4][2];
#pragma unroll
                for (int p = 0; p < 2; p++) {
                    uint32_t b = stage + bRowOff +
                                 (uint32_t)((h * 32 + p * 16) * LDAB);
                    uint32_t r0, r1, r2, r3;
                    ldsm_x4(r0, r1, r2, r3, b + OFF_BH);
                    bh[p * 2][0] = r0; bh[p * 2][1] = r1;
                    bh[p * 2 + 1][0] = r2; bh[p * 2 + 1][1] = r3;
                    ldsm_x4(r0, r1, r2, r3, b + OFF_BL);
                    bl[p * 2][0] = r0; bl[p * 2][1] = r1;
                    bl[p * 2 + 1][0] = r2; bl[p * 2 + 1][1] = r3;
                }
#pragma unroll
                for (int mf = 0; mf < 4; mf++) {
#pragma unroll
                    for (int nf = 0; nf < 4; nf++) {
                        float* c = acc[mf][h * 4 + nf];
                        mma16816(c[0], c[1], c[2], c[3],
                                 ah[mf][0], ah[mf][1], ah[mf][2], ah[mf][3],
                                 bh[nf][0], bh[nf][1]);
                        mma16816(c[0], c[1], c[2], c[3],
                                 ah[mf][0], ah[mf][1], ah[mf][2], ah[mf][3],
                                 bl[nf][0], bl[nf][1]);
                        mma16816(c[0], c[1], c[2], c[3],
                                 al[mf][0], al[mf][1], al[mf][2], al[mf][3],
                                 bh[nf][0], bh[nf][1]);
                    }
                }
            }
        }

        // fold this n-tile into running argmin (registers only)
#pragma unroll
        for (int nf = 0; nf < 8; nf++) {
            int n = n0 + warpN * 64 + nf * 8 + tg * 2;
            float cn0 = __ldg(&g_codeNorm[n]);
            float cn1 = __ldg(&g_codeNorm[n + 1]);
#pragma unroll
            for (int mf = 0; mf < 4; mf++) {
                float d0 = cn0 - 2.f * acc[mf][nf][0];
                float d1 = cn1 - 2.f * acc[mf][nf][1];
                float d2 = cn0 - 2.f * acc[mf][nf][2];
                float d3 = cn1 - 2.f * acc[mf][nf][3];
                if (d0 < best[2 * mf]) { best[2 * mf] = d0; bidx[2 * mf] = n; }
                if (d1 < best[2 * mf]) { best[2 * mf] = d1; bidx[2 * mf] = n + 1; }
                if (d2 < best[2 * mf + 1]) { best[2 * mf + 1] = d2; bidx[2 * mf + 1] = n; }
                if (d3 < best[2 * mf + 1]) { best[2 * mf + 1] = d3; bidx[2 * mf + 1] = n + 1; }
            }
        }
    }

    // both groups done; drain + full-CTA barrier before smem reuse
    CP_WAIT0();
    __syncthreads();

    // cross-thread reduce: row r owned by 16 threads
    // (2 groups x 2 N-warps x 4 tg); slot order ascends with codebook index.
    float* sV = reinterpret_cast<float*>(smem);            // [128][16]
    int*   sI = reinterpret_cast<int*>(smem + 128 * 16 * 4);
    const int slot = group * 8 + warpN * 4 + tg;
#pragma unroll
    for (int mf = 0; mf < 4; mf++) {
        int r0 = warpM * 64 + mf * 16 + grp8;
        sV[r0 * 16 + slot] = best[2 * mf];
        sI[r0 * 16 + slot] = bidx[2 * mf];
        sV[(r0 + 8) * 16 + slot] = best[2 * mf + 1];
        sI[(r0 + 8) * 16 + slot] = bidx[2 * mf + 1];
    }
    __syncthreads();
    if (tid < 128) {
        float bv = sV[tid * 16];
        int   bi = sI[tid * 16];
#pragma unroll
        for (int t = 1; t < 16; t++) {
            float v = sV[tid * 16 + t];
            int   ii = sI[tid * 16 + t];
            if (v < bv || (v == bv && ii < bi)) { bv = v; bi = ii; }
        }
        g_idx[m0 + tid] = bi;
    }
}

// ---------------------------------------------------------------------------
// att[t] = relu(dot(codebook[idx[t]], att_w[:,1])), + idx written as float
// ---------------------------------------------------------------------------
__global__ void att_kernel(const float* __restrict__ cb,
                           const float* __restrict__ att_w,
                           float* __restrict__ out_idx_f, int write_idx) {
    int gw   = (blockIdx.x * blockDim.x + threadIdx.x) >> 5;
    int lane = threadIdx.x & 31;
    if (gw >= MTOT) return;
    int idx = g_idx[gw];
    const float* row = cb + (size_t)idx * CDIM;
    float s = 0.f;
    for (int c = lane; c < CDIM; c += 32)
        s = fmaf(row[c], att_w[c * 3 + 1], s);
    for (int o = 16; o; o >>= 1) s += __shfl_down_sync(0xffffffffu, s, o);
    if (lane == 0) {
        g_att[gw] = fmaxf(s, 0.f);
        if (write_idx) out_idx_f[gw] = (float)idx;
    }
}

// ---------------------------------------------------------------------------
// softmax over L per batch -> g_mask
// ---------------------------------------------------------------------------
__global__ void softmax_kernel() {
    int b = blockIdx.x;
    int t = threadIdx.x;
    __shared__ float red[8];
    float v = (t < SEQL) ? g_att[b * SEQL + t] : -3.4e38f;

    float m = v;
    for (int o = 16; o; o >>= 1) m = fmaxf(m, __shfl_xor_sync(0xffffffffu, m, o));
    int lane = t & 31, wid = t >> 5;
    if (lane == 0) red[wid] = m;
    __syncthreads();
    if (wid == 0) {
        float x = (lane < 8) ? red[lane] : -3.4e38f;
        for (int o = 4; o; o >>= 1) x = fmaxf(x, __shfl_xor_sync(0xffffffffu, x, o));
        if (lane == 0) red[0] = x;
    }
    __syncthreads();
    float bmax = red[0];
    __syncthreads();

    float e = (t < SEQL) ? __expf(v - bmax) : 0.f;
    float s = e;
    for (int o = 16; o; o >>= 1) s += __shfl_xor_sync(0xffffffffu, s, o);
    if (lane == 0) red[wid] = s;
    __syncthreads();
    if (wid == 0) {
        float x = (lane < 8) ? red[lane] : 0.f;
        for (int o = 4; o; o >>= 1) x += __shfl_xor_sync(0xffffffffu, x, o);
        if (lane == 0) red[0] = x;
    }
    __syncthreads();
    float bsum = red[0];
    if (t < SEQL) g_mask[b * SEQL + t] = e / bsum;
}

// ---------------------------------------------------------------------------
// out[t,c] = codebook[idx[t]][c] + in[t,c] * mask[t]
// ---------------------------------------------------------------------------
__global__ void out_kernel(const float* __restrict__ in,
                           const float* __restrict__ cb,
                           float* __restrict__ out) {
    int t  = blockIdx.x;
    int c4 = threadIdx.x;          // 0..191
    float m = g_mask[t];
    int idx = g_idx[t];
    const float4* q4 = reinterpret_cast<const float4*>(cb + (size_t)idx * CDIM);
    const float4* x4 = reinterpret_cast<const float4*>(in + (size_t)t * CDIM);
    float4* o4 = reinterpret_cast<float4*>(out + (size_t)t * CDIM);
    float4 q = q4[c4];
    float4 x = x4[c4];
    o4[c4] = make_float4(fmaf(x.x, m, q.x), fmaf(x.y, m, q.y),
                         fmaf(x.z, m, q.z), fmaf(x.w, m, q.w));
}

// ---------------------------------------------------------------------------
extern "C" void kernel_launch(void* const* d_in, const int* in_sizes, int n_in,
                              void* d_out, int out_size) {
    const float* in_feas  = (const float*)d_in[0];   // [B, L, C]
    const float* codebook = (const float*)d_in[1];   // [K, C]
    const float* att_w    = (const float*)d_in[2];   // [1, C, 3]
    float* out = (float*)d_out;
    (void)in_sizes; (void)n_in;

    int write_idx = (out_size >= MTOT * CDIM + MTOT) ? 1 : 0;
    float* out_idx_f = out + (size_t)MTOT * CDIM;

    cudaFuncSetAttribute(vq_hmma_kernel,
                         cudaFuncAttributeMaxDynamicSharedMemorySize, SMEM_B);

    {
        int n4 = MTOT * CDIM / 4;   // 9,633,792
        convert_A_kernel<<<(n4 + 255) / 256, 256>>>(in_feas, n4);
    }
    {
        int n4 = KCODE * CDIM / 4;  // 393,216
        convert_B_kernel<<<(n4 + 255) / 256, 256>>>(codebook, n4);
    }
    codenorm_kernel<<<KCODE, 256>>>(codebook);

    vq_hmma_kernel<<<MTOT / 128, 256, SMEM_B>>>();

    att_kernel<<<(MTOT * 32 + 255) / 256, 256>>>(codebook, att_w, out_idx_f, write_idx);
    softmax_kernel<<<BATCH, 256>>>();
    out_kernel<<<MTOT, CDIM / 4>>>(in_feas, codebook, out);
}

// round 11
// speedup vs baseline: 1.2598x; 1.2296x over previous
#include <cuda_runtime.h>
#include <cuda_fp16.h>
#include <cstdint>
#include <math.h>

#define BATCH 256
#define SEQL  196
#define CDIM  768
#define KCODE 2048
#define MTOT  (BATCH*SEQL)   // 50176

// ---------------------------------------------------------------------------
// scratch (no cudaMalloc allowed)
// ---------------------------------------------------------------------------
__device__ float  g_codeNorm[KCODE];
__device__ int    g_idx[MTOT];
__device__ float  g_att[MTOT];
__device__ float  g_mask[MTOT];
__device__ __half g_Ahi[(size_t)MTOT * CDIM];   // 77 MB
__device__ __half g_Alo[(size_t)MTOT * CDIM];   // 77 MB
__device__ __half g_Bhi[(size_t)KCODE * CDIM];  // 3.1 MB
__device__ __half g_Blo[(size_t)KCODE * CDIM];  // 3.1 MB

// ---------------------------------------------------------------------------
// helpers
// ---------------------------------------------------------------------------
__device__ __forceinline__ uint32_t smem_u32(const void* p) {
    uint32_t a;
    asm("{ .reg .u64 t; cvta.to.shared.u64 t, %1; cvt.u32.u64 %0, t; }"
        : "=r"(a) : "l"(p));
    return a;
}

__device__ __forceinline__ void cp16(uint32_t saddr, const void* gaddr) {
    asm volatile("cp.async.ca.shared.global [%0], [%1], 16;"
                 :: "r"(saddr), "l"(gaddr));
}
#define CP_COMMIT() asm volatile("cp.async.commit_group;" ::: "memory")
#define CP_WAIT1()  asm volatile("cp.async.wait_group 1;" ::: "memory")
#define CP_WAIT0()  asm volatile("cp.async.wait_group 0;" ::: "memory")

__device__ __forceinline__ void ldsm_x4(uint32_t& r0, uint32_t& r1,
                                        uint32_t& r2, uint32_t& r3,
                                        uint32_t addr) {
    asm volatile("ldmatrix.sync.aligned.m8n8.x4.shared.b16 {%0,%1,%2,%3}, [%4];"
                 : "=r"(r0), "=r"(r1), "=r"(r2), "=r"(r3) : "r"(addr));
}

__device__ __forceinline__ void mma16816(float& c0, float& c1, float& c2, float& c3,
                                         uint32_t a0, uint32_t a1, uint32_t a2, uint32_t a3,
                                         uint32_t b0, uint32_t b1) {
    asm volatile("mma.sync.aligned.m16n8k16.row.col.f32.f16.f16.f32 "
                 "{%0,%1,%2,%3}, {%4,%5,%6,%7}, {%8,%9}, {%0,%1,%2,%3};"
                 : "+f"(c0), "+f"(c1), "+f"(c2), "+f"(c3)
                 : "r"(a0), "r"(a1), "r"(a2), "r"(a3), "r"(b0), "r"(b1));
}

// ---------------------------------------------------------------------------
// convert: float -> (fp16 hi, fp16 lo)
// ---------------------------------------------------------------------------
__global__ void convert_A_kernel(const float* __restrict__ src, int n4) {
    int i = blockIdx.x * blockDim.x + threadIdx.x;
    if (i >= n4) return;
    float4 v = reinterpret_cast<const float4*>(src)[i];
    __half h0 = __float2half_rn(v.x), h1 = __float2half_rn(v.y);
    __half h2 = __float2half_rn(v.z), h3 = __float2half_rn(v.w);
    __half l0 = __float2half_rn(v.x - __half2float(h0));
    __half l1 = __float2half_rn(v.y - __half2float(h1));
    __half l2 = __float2half_rn(v.z - __half2float(h2));
    __half l3 = __float2half_rn(v.w - __half2float(h3));
    __half2* hp = reinterpret_cast<__half2*>(g_Ahi) + 2 * (size_t)i;
    __half2* lp = reinterpret_cast<__half2*>(g_Alo) + 2 * (size_t)i;
    hp[0] = __halves2half2(h0, h1); hp[1] = __halves2half2(h2, h3);
    lp[0] = __halves2half2(l0, l1); lp[1] = __halves2half2(l2, l3);
}

__global__ void convert_B_kernel(const float* __restrict__ src, int n4) {
    int i = blockIdx.x * blockDim.x + threadIdx.x;
    if (i >= n4) return;
    float4 v = reinterpret_cast<const float4*>(src)[i];
    __half h0 = __float2half_rn(v.x), h1 = __float2half_rn(v.y);
    __half h2 = __float2half_rn(v.z), h3 = __float2half_rn(v.w);
    __half l0 = __float2half_rn(v.x - __half2float(h0));
    __half l1 = __float2half_rn(v.y - __half2float(h1));
    __half l2 = __float2half_rn(v.z - __half2float(h2));
    __half l3 = __float2half_rn(v.w - __half2float(h3));
    __half2* hp = reinterpret_cast<__half2*>(g_Bhi) + 2 * (size_t)i;
    __half2* lp = reinterpret_cast<__half2*>(g_Blo) + 2 * (size_t)i;
    hp[0] = __halves2half2(h0, h1); hp[1] = __halves2half2(h2, h3);
    lp[0] = __halves2half2(l0, l1); lp[1] = __halves2half2(l2, l3);
}

// ---------------------------------------------------------------------------
// codebook row norms ||e||^2 (fp32 exact)
// ---------------------------------------------------------------------------
__global__ void codenorm_kernel(const float* __restrict__ cb) {
    int k = blockIdx.x;
    const float* row = cb + (size_t)k * CDIM;
    float s = 0.f;
    for (int c = threadIdx.x; c < CDIM; c += blockDim.x) {
        float v = row[c];
        s += v * v;
    }
    for (int o = 16; o; o >>= 1) s += __shfl_down_sync(0xffffffffu, s, o);
    __shared__ float red[8];
    int lane = threadIdx.x & 31, wid = threadIdx.x >> 5;
    if (lane == 0) red[wid] = s;
    __syncthreads();
    if (threadIdx.x == 0) {
        float t = 0.f;
        for (int w = 0; w < (int)(blockDim.x >> 5); w++) t += red[w];
        g_codeNorm[k] = t;
    }
}

// ---------------------------------------------------------------------------
// HMMA distance GEMM + fused argmin, 2-CTA/SM version.
// CTA: 128 threads = 4 warps (1M x 4N), tile 64(M) x 256(N), warp tile 64x64.
// 3-stage cp.async pipeline, lookahead 1, issue-before-wait, one sync/step.
// Two CTAs co-resident per SM (launch_bounds(128,2), 92KB smem each):
// their barrier phases decouple, overlapping LDSM bursts with MMA bursts.
// dot = Ahi*Bhi + Ahi*Blo + Alo*Bhi (fp32 acc), d = ||e||^2 - 2*dot.
// ---------------------------------------------------------------------------
#define LDAB   48                   // bytes per SMEM row (16 halfs + 8 pad)
#define AMAT_B (64 * LDAB)          // 3072
#define BMAT_B (256 * LDAB)         // 12288
#define OFF_AH 0
#define OFF_AL (AMAT_B)
#define OFF_BH (2 * AMAT_B)
#define OFF_BL (2 * AMAT_B + BMAT_B)
#define STAGE_B (2 * AMAT_B + 2 * BMAT_B)   // 30720
#define NSTAGE  3
#define SMEM_B  (NSTAGE * STAGE_B)          // 92160
#define KSTEPS  (CDIM / 16)         // 48
#define NTILES  (KCODE / 256)       // 8

__global__ void __launch_bounds__(128, 2) vq_hmma_kernel() {
    extern __shared__ char smem[];
    const uint32_t sb = smem_u32(smem);

    const int tid   = threadIdx.x;
    const int lane  = tid & 31;
    const int warpN = tid >> 5;        // 0..3
    const int tg    = lane & 3;        // 0..3
    const int grp8  = lane >> 2;       // 0..7
    const int m0    = blockIdx.x * 64;

    // cp.async mapping: thread -> 10 x 16B chunks per stage:
    //   A row (tid>>1, half tid&1): Ahi + Alo           (2)
    //   B rows (tid>>1)+{0,64,128,192}, half tid&1: hi   (4)
    //   same rows: lo                                    (4)
    const int ldRow  = tid >> 1;       // 0..63
    const int ldHalf = tid & 1;        // 0..1
    const uint32_t aOff = (uint32_t)(ldRow * LDAB + ldHalf * 16);
    const __half* AhiBase = g_Ahi + (size_t)(m0 + ldRow) * CDIM + ldHalf * 8;
    const __half* AloBase = g_Alo + (size_t)(m0 + ldRow) * CDIM + ldHalf * 8;
    uint32_t bOff[4];
    size_t   bG[4];
#pragma unroll
    for (int r = 0; r < 4; r++) {
        bOff[r] = (uint32_t)((ldRow + r * 64) * LDAB + ldHalf * 16);
        bG[r]   = (size_t)(ldRow + r * 64) * CDIM + ldHalf * 8;
    }

    // ldmatrix addresses (within a stage, relative)
    const uint32_t aRowOff =
        (uint32_t)((lane & 15) * LDAB + (lane >> 4) * 16);
    const uint32_t bRowOff =
        (uint32_t)((warpN * 64 + ((lane >> 4) << 3) + (lane & 7)) * LDAB +
                   ((lane >> 3) & 1) * 16);

    // per-thread argmin: 8 owned row-slots (4 mf x 2 halves)
    float best[8];
    int   bidx[8];
#pragma unroll
    for (int i = 0; i < 8; i++) { best[i] = 3.4e38f; bidx[i] = 0; }

    // issue cursor
    int in = 0, ik = 0;

    // prologue: issue data step 0 into stage 0
    {
        uint32_t st = sb;
        const __half* bh0 = g_Bhi;
        const __half* bl0 = g_Blo;
        cp16(st + OFF_AH + aOff, AhiBase);
        cp16(st + OFF_AL + aOff, AloBase);
#pragma unroll
        for (int r = 0; r < 4; r++) {
            cp16(st + OFF_BH + bOff[r], bh0 + bG[r]);
            cp16(st + OFF_BL + bOff[r], bl0 + bG[r]);
        }
        CP_COMMIT();
        if (++ik == KSTEPS) { ik = 0; in++; }
    }

    for (int nt = 0; nt < NTILES; nt++) {
        const int n0 = nt * 256;

        float acc[4][8][4];
#pragma unroll
        for (int mf = 0; mf < 4; mf++)
#pragma unroll
            for (int nf = 0; nf < 8; nf++)
#pragma unroll
                for (int c = 0; c < 4; c++) acc[mf][nf][c] = 0.f;

        for (int ks = 0; ks < KSTEPS; ks++) {
            const int g = nt * KSTEPS + ks;

            // issue data g+1 into stage (g+1)%3 BEFORE the wait.
            // stage (g+1)%3 was consumed at step g-2; all warps passed
            // barrier g-1 (after their compute of g-2) -> safe to refill.
            if (in < NTILES) {
                uint32_t st = sb + (uint32_t)((g + 1) % NSTAGE) * STAGE_B;
                int gk = ik * 16;
                const __half* bh0 = g_Bhi + (size_t)in * 256 * CDIM;
                const __half* bl0 = g_Blo + (size_t)in * 256 * CDIM;
                cp16(st + OFF_AH + aOff, AhiBase + gk);
                cp16(st + OFF_AL + aOff, AloBase + gk);
#pragma unroll
                for (int r = 0; r < 4; r++) {
                    cp16(st + OFF_BH + bOff[r], bh0 + bG[r] + gk);
                    cp16(st + OFF_BL + bOff[r], bl0 + bG[r] + gk);
                }
                if (++ik == KSTEPS) { ik = 0; in++; }
            }
            CP_COMMIT();   // unconditional: keeps group counting exact at tail

            CP_WAIT1();    // newest outstanding = g+1 -> data g ready
            __syncthreads();

            const uint32_t stage = sb + (uint32_t)(g % NSTAGE) * STAGE_B;

            uint32_t ah[4][4], al[4][4];
#pragma unroll
            for (int mf = 0; mf < 4; mf++) {
                uint32_t a = stage + aRowOff + (uint32_t)(mf * 16 * LDAB);
                ldsm_x4(ah[mf][0], ah[mf][1], ah[mf][2], ah[mf][3], a + OFF_AH);
                ldsm_x4(al[mf][0], al[mf][1], al[mf][2], al[mf][3], a + OFF_AL);
            }

            // B in two 32-column halves to cap register liveness
#pragma unroll
            for (int h = 0; h < 2; h++) {
                uint32_t bh[4][2], bl[4][2];
#pragma unroll
                for (int p = 0; p < 2; p++) {
                    uint32_t b = stage + bRowOff +
                                 (uint32_t)((h * 32 + p * 16) * LDAB);
                    uint32_t r0, r1, r2, r3;
                    ldsm_x4(r0, r1, r2, r3, b + OFF_BH);
                    bh[p * 2][0] = r0; bh[p * 2][1] = r1;
                    bh[p * 2 + 1][0] = r2; bh[p * 2 + 1][1] = r3;
                    ldsm_x4(r0, r1, r2, r3, b + OFF_BL);
                    bl[p * 2][0] = r0; bl[p * 2][1] = r1;
                    bl[p * 2 + 1][0] = r2; bl[p * 2 + 1][1] = r3;
                }
#pragma unroll
                for (int mf = 0; mf < 4; mf++) {
#pragma unroll
                    for (int nf = 0; nf < 4; nf++) {
                        float* c = acc[mf][h * 4 + nf];
                        mma16816(c[0], c[1], c[2], c[3],
                                 ah[mf][0], ah[mf][1], ah[mf][2], ah[mf][3],
                                 bh[nf][0], bh[nf][1]);
                        mma16816(c[0], c[1], c[2], c[3],
                                 ah[mf][0], ah[mf][1], ah[mf][2], ah[mf][3],
                                 bl[nf][0], bl[nf][1]);
                        mma16816(c[0], c[1], c[2], c[3],
                                 al[mf][0], al[mf][1], al[mf][2], al[mf][3],
                                 bh[nf][0], bh[nf][1]);
                    }
                }
            }
        }

        // fold this n-tile into running argmin (registers only)
#pragma unroll
        for (int nf = 0; nf < 8; nf++) {
            int n = n0 + warpN * 64 + nf * 8 + tg * 2;
            float cn0 = __ldg(&g_codeNorm[n]);
            float cn1 = __ldg(&g_codeNorm[n + 1]);
#pragma unroll
            for (int mf = 0; mf < 4; mf++) {
                float d0 = cn0 - 2.f * acc[mf][nf][0];
                float d1 = cn1 - 2.f * acc[mf][nf][1];
                float d2 = cn0 - 2.f * acc[mf][nf][2];
                float d3 = cn1 - 2.f * acc[mf][nf][3];
                if (d0 < best[2 * mf]) { best[2 * mf] = d0; bidx[2 * mf] = n; }
                if (d1 < best[2 * mf]) { best[2 * mf] = d1; bidx[2 * mf] = n + 1; }
                if (d2 < best[2 * mf + 1]) { best[2 * mf + 1] = d2; bidx[2 * mf + 1] = n; }
                if (d3 < best[2 * mf + 1]) { best[2 * mf + 1] = d3; bidx[2 * mf + 1] = n + 1; }
            }
        }
    }

    // drain remaining (empty) groups before reusing smem
    CP_WAIT0();
    __syncthreads();

    // cross-thread reduce: row r (0..63) owned by 16 threads (4 N-warps x 4 tg)
    float* sV = reinterpret_cast<float*>(smem);            // [64][16]
    int*   sI = reinterpret_cast<int*>(smem + 64 * 16 * 4);
    const int slot = warpN * 4 + tg;
#pragma unroll
    for (int mf = 0; mf < 4; mf++) {
        int r0 = mf * 16 + grp8;
        sV[r0 * 16 + slot] = best[2 * mf];
        sI[r0 * 16 + slot] = bidx[2 * mf];
        sV[(r0 + 8) * 16 + slot] = best[2 * mf + 1];
        sI[(r0 + 8) * 16 + slot] = bidx[2 * mf + 1];
    }
    __syncthreads();
    if (tid < 64) {
        float bv = sV[tid * 16];
        int   bi = sI[tid * 16];
#pragma unroll
        for (int t = 1; t < 16; t++) {
            float v = sV[tid * 16 + t];
            int   ii = sI[tid * 16 + t];
            if (v < bv || (v == bv && ii < bi)) { bv = v; bi = ii; }
        }
        g_idx[m0 + tid] = bi;
    }
}

// ---------------------------------------------------------------------------
// att[t] = relu(dot(codebook[idx[t]], att_w[:,1])), + idx written as float
// ---------------------------------------------------------------------------
__global__ void att_kernel(const float* __restrict__ cb,
                           const float* __restrict__ att_w,
                           float* __restrict__ out_idx_f, int write_idx) {
    int gw   = (blockIdx.x * blockDim.x + threadIdx.x) >> 5;
    int lane = threadIdx.x & 31;
    if (gw >= MTOT) return;
    int idx = g_idx[gw];
    const float* row = cb + (size_t)idx * CDIM;
    float s = 0.f;
    for (int c = lane; c < CDIM; c += 32)
        s = fmaf(row[c], att_w[c * 3 + 1], s);
    for (int o = 16; o; o >>= 1) s += __shfl_down_sync(0xffffffffu, s, o);
    if (lane == 0) {
        g_att[gw] = fmaxf(s, 0.f);
        if (write_idx) out_idx_f[gw] = (float)idx;
    }
}

// ---------------------------------------------------------------------------
// softmax over L per batch -> g_mask
// ---------------------------------------------------------------------------
__global__ void softmax_kernel() {
    int b = blockIdx.x;
    int t = threadIdx.x;
    __shared__ float red[8];
    float v = (t < SEQL) ? g_att[b * SEQL + t] : -3.4e38f;

    float m = v;
    for (int o = 16; o; o >>= 1) m = fmaxf(m, __shfl_xor_sync(0xffffffffu, m, o));
    int lane = t & 31, wid = t >> 5;
    if (lane == 0) red[wid] = m;
    __syncthreads();
    if (wid == 0) {
        float x = (lane < 8) ? red[lane] : -3.4e38f;
        for (int o = 4; o; o >>= 1) x = fmaxf(x, __shfl_xor_sync(0xffffffffu, x, o));
        if (lane == 0) red[0] = x;
    }
    __syncthreads();
    float bmax = red[0];
    __syncthreads();

    float e = (t < SEQL) ? __expf(v - bmax) : 0.f;
    float s = e;
    for (int o = 16; o; o >>= 1) s += __shfl_xor_sync(0xffffffffu, s, o);
    if (lane == 0) red[wid] = s;
    __syncthreads();
    if (wid == 0) {
        float x = (lane < 8) ? red[lane] : 0.f;
        for (int o = 4; o; o >>= 1) x += __shfl_xor_sync(0xffffffffu, x, o);
        if (lane == 0) red[0] = x;
    }
    __syncthreads();
    float bsum = red[0];
    if (t < SEQL) g_mask[b * SEQL + t] = e / bsum;
}

// ---------------------------------------------------------------------------
// out[t,c] = codebook[idx[t]][c] + in[t,c] * mask[t]
// ---------------------------------------------------------------------------
__global__ void out_kernel(const float* __restrict__ in,
                           const float* __restrict__ cb,
                           float* __restrict__ out) {
    int t  = blockIdx.x;
    int c4 = threadIdx.x;          // 0..191
    float m = g_mask[t];
    int idx = g_idx[t];
    const float4* q4 = reinterpret_cast<const float4*>(cb + (size_t)idx * CDIM);
    const float4* x4 = reinterpret_cast<const float4*>(in + (size_t)t * CDIM);
    float4* o4 = reinterpret_cast<float4*>(out + (size_t)t * CDIM);
    float4 q = q4[c4];
    float4 x = x4[c4];
    o4[c4] = make_float4(fmaf(x.x, m, q.x), fmaf(x.y, m, q.y),
                         fmaf(x.z, m, q.z), fmaf(x.w, m, q.w));
}

// ---------------------------------------------------------------------------
extern "C" void kernel_launch(void* const* d_in, const int* in_sizes, int n_in,
                              void* d_out, int out_size) {
    const float* in_feas  = (const float*)d_in[0];   // [B, L, C]
    const float* codebook = (const float*)d_in[1];   // [K, C]
    const float* att_w    = (const float*)d_in[2];   // [1, C, 3]
    float* out = (float*)d_out;
    (void)in_sizes; (void)n_in;

    int write_idx = (out_size >= MTOT * CDIM + MTOT) ? 1 : 0;
    float* out_idx_f = out + (size_t)MTOT * CDIM;

    cudaFuncSetAttribute(vq_hmma_kernel,
                         cudaFuncAttributeMaxDynamicSharedMemorySize, SMEM_B);

    {
        int n4 = MTOT * CDIM / 4;   // 9,633,792
        convert_A_kernel<<<(n4 + 255) / 256, 256>>>(in_feas, n4);
    }
    {
        int n4 = KCODE * CDIM / 4;  // 393,216
        convert_B_kernel<<<(n4 + 255) / 256, 256>>>(codebook, n4);
    }
    codenorm_kernel<<<KCODE, 256>>>(codebook);

    vq_hmma_kernel<<<MTOT / 64, 128, SMEM_B>>>();

    att_kernel<<<(MTOT * 32 + 255) / 256, 256>>>(codebook, att_w, out_idx_f, write_idx);
    softmax_kernel<<<BATCH, 256>>>();
    out_kernel<<<MTOT, CDIM / 4>>>(in_feas, codebook, out);
}